// round 8
// baseline (speedup 1.0000x reference)
#include <cuda_runtime.h>
#include <cuda_bf16.h>
#include <math.h>

#define BB   16
#define KK   32
#define HH   28
#define WW   28
#define HID  64
#define OUT  64
#define NIMG (BB*KK)          // 512

typedef unsigned long long u64;

// ---------------- scratch ----------------
__device__ float g_h1[NIMG * 32 * 14 * 14];
__device__ float g_h2[NIMG * 64 * 7 * 7];
__device__ float g_feat[NIMG * HID];
__device__ float g_part[NIMG * OUT];

// ---------------- packed fp32x2 helpers ----------------
__device__ __forceinline__ u64 pack2(float x, float y) {
    u64 r; asm("mov.b64 %0,{%1,%2};" : "=l"(r) : "f"(x), "f"(y)); return r;
}
__device__ __forceinline__ void unpack2(u64 p, float& x, float& y) {
    asm("mov.b64 {%0,%1},%2;" : "=f"(x), "=f"(y) : "l"(p));
}
__device__ __forceinline__ u64 ffma2(u64 a, u64 b, u64 c) {
    u64 d; asm("fma.rn.f32x2 %0,%1,%2,%3;" : "=l"(d) : "l"(a), "l"(b), "l"(c)); return d;
}

// =========================================================================
// Kernel 1: conv1 (1->32, 3x3 SAME) + relu + maxpool2
// =========================================================================
__global__ __launch_bounds__(256) void conv1_kernel(
    const float* __restrict__ x, const float* __restrict__ w,
    const float* __restrict__ bias)
{
    __shared__ float sin1[30 * 30];
    __shared__ float sw1[32 * 9];
    __shared__ float sb1[32];

    const int img = blockIdx.x;
    const int tid = threadIdx.x;

    for (int i = tid; i < 900; i += 256) sin1[i] = 0.f;
    for (int i = tid; i < 288; i += 256) sw1[i] = w[i];
    if (tid < 32) sb1[tid] = bias[tid];
    __syncthreads();
    for (int i = tid; i < 784; i += 256) {
        int y = i / 28, xx = i % 28;
        sin1[(y + 1) * 30 + xx + 1] = x[img * 784 + i];
    }
    __syncthreads();

    for (int item = tid; item < 32 * 196; item += 256) {
        int c = item / 196, p = item % 196;
        int oy = p / 14, ox = p % 14;
        const float* wp = sw1 + c * 9;
        const float bv = sb1[c];
        float m = 0.f;
        #pragma unroll
        for (int py = 0; py < 2; py++) {
            #pragma unroll
            for (int px = 0; px < 2; px++) {
                int r = 2 * oy + py, col = 2 * ox + px;
                float s = bv;
                #pragma unroll
                for (int ky = 0; ky < 3; ky++)
                    #pragma unroll
                    for (int kx = 0; kx < 3; kx++)
                        s += sin1[(r + ky) * 30 + col + kx] * wp[ky * 3 + kx];
                m = fmaxf(m, s);
            }
        }
        g_h1[img * (32 * 196) + item] = m;
    }
}

// =========================================================================
// Kernel 2: conv2 (32->64) + relu + maxpool2.
// Input stored PRE-DUPLICATED in smem ([v,v] pairs): one warp-uniform
// LDS.64 yields a ready packed operand -> ZERO pack/MOV in inner loop.
// warp = pooled position (warp-uniform), lane = ch-pair.
// 448 threads, 1 block/SM (smem 139KB). 49 positions in 4 s-iters.
// =========================================================================
#define CONV2_SMEM ((16384 + 18432 + 64) * 4)
__global__ __launch_bounds__(448, 1) void conv2_kernel(
    const float* __restrict__ w, const float* __restrict__ bias)
{
    extern __shared__ float sm2[];
    float* sdin = sm2;                 // [ic][16*16][2] duplicated pairs
    float* sw2  = sm2 + 16384;         // [ic*9+r][64ch]
    float* sb2  = sw2 + 18432;

    const int img = blockIdx.x;
    const int tid = threadIdx.x;
    const int nt  = 448;

    for (int i = tid; i < 16384; i += nt) sdin[i] = 0.f;
    for (int idx = tid; idx < 18432; idx += nt) {
        int f = idx >> 6, c = idx & 63;
        int ic = f / 9, r = f % 9;
        sw2[idx] = w[(c * 32 + ic) * 9 + r];
    }
    if (tid < 64) sb2[tid] = bias[tid];
    __syncthreads();
    for (int i = tid; i < 32 * 196; i += nt) {
        int ic = i / 196, p = i % 196;
        int y = p / 14, xx = p % 14;
        float v = g_h1[img * (32 * 196) + i];
        int di = (ic * 256 + (y + 1) * 16 + xx + 1) * 2;
        *(u64*)(sdin + di) = pack2(v, v);
    }
    __syncthreads();

    const int wid  = tid >> 5;         // 0..13
    const int lane = tid & 31;
    const int c0   = lane * 2;
    const float b0 = sb2[c0], b1 = sb2[c0 + 1];

    #pragma unroll
    for (int s = 0; s < 4; s++) {
        const int pos = wid + 14 * s;   // warp-uniform
        if (pos < 49) {
            const int oy = pos / 7, ox = pos % 7;
            const int iy = 2 * oy, ix = 2 * ox;

            u64 acc[4];
            #pragma unroll
            for (int p = 0; p < 4; p++) acc[p] = 0ull;

            for (int ic = 0; ic < 32; ic++) {
                const float* ip = sdin + (ic * 256 + iy * 16 + ix) * 2;
                u64 pa[4][4];           // pre-packed (v,v), broadcast loads
                #pragma unroll
                for (int r = 0; r < 4; r++)
                    #pragma unroll
                    for (int cc = 0; cc < 4; cc++)
                        pa[r][cc] = *(const u64*)(ip + (r * 16 + cc) * 2);

                const float* wic = sw2 + ic * 576 + c0;
                #pragma unroll
                for (int ky = 0; ky < 3; ky++) {
                    #pragma unroll
                    for (int kx = 0; kx < 3; kx++) {
                        u64 wv = *(const u64*)(wic + (ky * 3 + kx) * 64);
                        acc[0] = ffma2(pa[ky][kx],         wv, acc[0]);
                        acc[1] = ffma2(pa[ky][kx + 1],     wv, acc[1]);
                        acc[2] = ffma2(pa[ky + 1][kx],     wv, acc[2]);
                        acc[3] = ffma2(pa[ky + 1][kx + 1], wv, acc[3]);
                    }
                }
            }
            float a0[4], a1[4];
            #pragma unroll
            for (int p = 0; p < 4; p++) unpack2(acc[p], a0[p], a1[p]);
            float m0 = fmaxf(fmaxf(a0[0], a0[1]), fmaxf(a0[2], a0[3])) + b0;
            float m1 = fmaxf(fmaxf(a1[0], a1[1]), fmaxf(a1[2], a1[3])) + b1;
            g_h2[img * 3136 + c0 * 49 + pos]       = fmaxf(m0, 0.f);
            g_h2[img * 3136 + (c0 + 1) * 49 + pos] = fmaxf(m1, 0.f);
        }
    }
}

// =========================================================================
// Kernel 3: fc, weight-stationary. 64 blocks x 8 images.
// =========================================================================
#define FC_CHUNK 392
#define FC_WPAD  66
#define FC_SMEM  ((8 * 3136 + FC_CHUNK * FC_WPAD) * 4)
__global__ __launch_bounds__(256) void fc_kernel(
    const float* __restrict__ fcw, const float* __restrict__ fcb)
{
    extern __shared__ float smf[];
    float* sact = smf;                  // [8][3136]
    float* swc  = smf + 8 * 3136;       // [392][66] transposed chunk

    const int tid  = threadIdx.x;
    const int img0 = blockIdx.x * 8;

    for (int idx = tid; idx < 8 * 3136; idx += 256)
        sact[idx] = g_h2[img0 * 3136 + idx];

    const int o2 = (tid & 31) * 2;
    const int q  = tid >> 5;

    u64 acc[8];
    #pragma unroll
    for (int im = 0; im < 8; im++) acc[im] = 0ull;

    for (int ch = 0; ch < 8; ch++) {
        __syncthreads();
        for (int idx = tid; idx < 64 * FC_CHUNK; idx += 256) {
            int o = idx / FC_CHUNK, i = idx % FC_CHUNK;
            swc[i * FC_WPAD + o] = fcw[(size_t)o * 3136 + ch * FC_CHUNK + i];
        }
        __syncthreads();

        const int ibase = q * 49;
        #pragma unroll 7
        for (int t = 0; t < 49; t++) {
            int i = ibase + t;
            u64 wv = *(const u64*)(swc + i * FC_WPAD + o2);
            int gi = ch * FC_CHUNK + i;
            #pragma unroll
            for (int im = 0; im < 8; im++) {
                float a = sact[im * 3136 + gi];
                acc[im] = ffma2(pack2(a, a), wv, acc[im]);
            }
        }
    }
    __syncthreads();

    float* sred = swc;
    #pragma unroll
    for (int im = 0; im < 8; im++) {
        float a0, a1;
        unpack2(acc[im], a0, a1);
        sred[q * 512 + im * 64 + o2]     = a0;
        sred[q * 512 + im * 64 + o2 + 1] = a1;
    }
    __syncthreads();
    for (int idx = tid; idx < 512; idx += 256) {
        int im = idx >> 6, o = idx & 63;
        float s = 0.f;
        #pragma unroll
        for (int qq = 0; qq < 8; qq++) s += sred[qq * 512 + idx];
        g_feat[(img0 + im) * 64 + o] = fmaxf(s + fcb[o], 0.f);
    }
}

// =========================================================================
// Kernel 4: Eq3to3 + relu + mean(ijk). Warp-tile rank-1 outer product,
// 10 warps = 10 upper-triangle 8x8 jk-tiles, lane = e.
// =========================================================================
#define EQ_NT 320
#define EQ_SMEM ((2304 + 64 + 3*4352 + 2*2048 + 64 + 640) * 4)
__global__ __launch_bounds__(EQ_NT, 2) void eq_kernel(
    const float* __restrict__ eqw, const float* __restrict__ eqb)
{
    extern __shared__ float sm[];
    float* sat  = sm;            // [d][k] pad 36 : 2304
    float* sAb  = sat + 2304;    // 64
    float* sV   = sAb + 64;      // [d][e] pad 68 : 4352
    float* sCk  = sV  + 4352;
    float* sCj  = sCk + 4352;
    float* sgk  = sCj + 4352;    // [k][e] : 2048
    float* sgj  = sgk + 2048;    // [j][e] : 2048
    float* ssb  = sgj + 2048;    // 64
    float* sred = ssb + 64;      // [10 warps][64]

    const int b   = blockIdx.x >> 5;
    const int ii  = blockIdx.x & 31;
    const int tid = threadIdx.x;

    const float* fb = g_feat + b * KK * HID;
    for (int idx = tid; idx < 2048; idx += EQ_NT) {
        int k = idx >> 6, d = idx & 63;
        sat[d * 36 + k] = fb[idx];
    }
    __syncthreads();
    if (tid < 64) {
        const float* row = sat + tid * 36;
        float s = 0.f;
        #pragma unroll
        for (int k = 0; k < 32; k++) s += row[k];
        sAb[tid] = s * (1.0f / 32.0f);
    }
    __syncthreads();

    for (int idx = tid; idx < 4096; idx += EQ_NT) {
        int d = idx >> 6, e = idx & 63;
        const float4* wp = (const float4*)(eqw + (size_t)idx * 8);
        float4 wA = wp[0];   // w0 w1 w2 w3
        float4 wB = wp[1];   // w4 w5 w6 w7
        float ai = sat[d * 36 + ii], ab = sAb[d];
        sV [d * 68 + e] = wA.x * ai + wA.y * ab;
        sCk[d * 68 + e] = ab * (wA.z * ai + wB.x * ab);
        sCj[d * 68 + e] = ab * (wA.w * ai + wB.y * ab);
    }
    if (tid < 64) {
        int e = tid;
        float s = 0.f;
        for (int d = 0; d < 64; d++) {
            float ab = sAb[d];
            float2 w67 = *(const float2*)(eqw + ((size_t)(d * 64 + e)) * 8 + 6);
            s += ab * ab * (w67.x * sat[d * 36 + ii] + w67.y * ab);
        }
        ssb[e] = s + eqb[e];
    }
    __syncthreads();

    for (int idx = tid; idx < 2048; idx += EQ_NT) {
        int k = idx >> 6, e = idx & 63;
        float s1 = 0.f, s2 = 0.f;
        #pragma unroll 8
        for (int d = 0; d < 64; d++) {
            float ak = sat[d * 36 + k];
            s1 += sCk[d * 68 + e] * ak;
            s2 += sCj[d * 68 + e] * ak;
        }
        sgk[k * 64 + e] = s1;
        sgj[k * 64 + e] = s2;
    }
    __syncthreads();

    const int w    = tid >> 5;
    const int lane = tid & 31;

    const u64 JT = 0x3221110000ull;
    const u64 KT = 0x3323213210ull;
    const int jt = (int)((JT >> (4 * w)) & 15);
    const int kt = (int)((KT >> (4 * w)) & 15);
    const int j0 = jt * 8;
    const int k0 = kt * 8;
    const bool diag = (jt == kt);

    float esum0 = 0.f, esum1 = 0.f;

    #pragma unroll
    for (int pass = 0; pass < 2; pass++) {
        const int e = lane + 32 * pass;

        u64 acc[8][4];
        #pragma unroll
        for (int jj = 0; jj < 8; jj++)
            #pragma unroll
            for (int kp = 0; kp < 4; kp++) acc[jj][kp] = 0ull;

        for (int d = 0; d < 64; d++) {
            const float* rd = sat + d * 36;
            float vl = sV[d * 68 + e];
            float aj[8];
            #pragma unroll
            for (int jj = 0; jj < 8; jj++) aj[jj] = rd[j0 + jj];
            u64 ak[4];
            #pragma unroll
            for (int kp = 0; kp < 4; kp++)
                ak[kp] = *(const u64*)(rd + k0 + 2 * kp);

            #pragma unroll
            for (int jj = 0; jj < 8; jj++) {
                float tv = aj[jj] * vl;
                u64 tp = pack2(tv, tv);
                acc[jj][0] = ffma2(tp, ak[0], acc[jj][0]);
                acc[jj][1] = ffma2(tp, ak[1], acc[jj][1]);
                acc[jj][2] = ffma2(tp, ak[2], acc[jj][2]);
                acc[jj][3] = ffma2(tp, ak[3], acc[jj][3]);
            }
        }

        const float sbv = ssb[e];
        float es = 0.f;
        #pragma unroll
        for (int jj = 0; jj < 8; jj++) {
            const int j = j0 + jj;
            const float gjj = sgj[j * 64 + e];
            const float gkj = sgk[j * 64 + e];
            #pragma unroll
            for (int kp = 0; kp < 4; kp++) {
                float a0, a1;
                unpack2(acc[jj][kp], a0, a1);
                const int ka = k0 + 2 * kp;
                const int kb = ka + 1;
                float gkka = sgk[ka * 64 + e], gjka = sgj[ka * 64 + e];
                float gkkb = sgk[kb * 64 + e], gjkb = sgj[kb * 64 + e];
                float p0 = a0 + gjj + gkka + sbv;
                float q0 = a0 + gjka + gkj + sbv;
                float p1 = a1 + gjj + gkkb + sbv;
                float q1 = a1 + gjkb + gkj + sbv;
                if (!diag || ka >= j) es += fmaxf(p0, 0.f);
                if (!diag || ka >  j) es += fmaxf(q0, 0.f);
                if (!diag || kb >= j) es += fmaxf(p1, 0.f);
                if (!diag || kb >  j) es += fmaxf(q1, 0.f);
            }
        }
        if (pass == 0) esum0 = es; else esum1 = es;
    }

    sred[w * 64 + lane]      = esum0;
    sred[w * 64 + lane + 32] = esum1;
    __syncthreads();
    if (tid < 64) {
        float s = 0.f;
        #pragma unroll
        for (int g = 0; g < 10; g++) s += sred[g * 64 + tid];
        g_part[blockIdx.x * 64 + tid] = s;
    }
}

// =========================================================================
// Kernel 5: final
// =========================================================================
__global__ __launch_bounds__(64) void final_kernel(
    const float* __restrict__ outw, const float* __restrict__ outb,
    float* __restrict__ out)
{
    __shared__ float red[64];
    const int b = blockIdx.x, e = threadIdx.x;
    float s = 0.f;
    #pragma unroll
    for (int i = 0; i < 32; i++) s += g_part[(b * 32 + i) * 64 + e];
    float x8 = s * (1.0f / 32768.0f);
    red[e] = fmaxf(x8, 0.f) * outw[e];
    __syncthreads();
    #pragma unroll
    for (int off = 32; off; off >>= 1) {
        if (e < off) red[e] += red[e + off];
        __syncthreads();
    }
    if (e == 0) out[b] = red[0] + outb[0];
}

// =========================================================================
extern "C" void kernel_launch(void* const* d_in, const int* in_sizes, int n_in,
                              void* d_out, int out_size)
{
    const float* x    = (const float*)d_in[0];
    const float* c1w  = (const float*)d_in[1];
    const float* c1b  = (const float*)d_in[2];
    const float* c2w  = (const float*)d_in[3];
    const float* c2b  = (const float*)d_in[4];
    const float* fcw  = (const float*)d_in[5];
    const float* fcb  = (const float*)d_in[6];
    const float* eqw  = (const float*)d_in[7];
    const float* eqb  = (const float*)d_in[8];
    const float* outw = (const float*)d_in[9];
    const float* outb = (const float*)d_in[10];
    float* out = (float*)d_out;

    cudaFuncSetAttribute(conv2_kernel, cudaFuncAttributeMaxDynamicSharedMemorySize, CONV2_SMEM);
    cudaFuncSetAttribute(fc_kernel,    cudaFuncAttributeMaxDynamicSharedMemorySize, FC_SMEM);
    cudaFuncSetAttribute(eq_kernel,    cudaFuncAttributeMaxDynamicSharedMemorySize, EQ_SMEM);

    conv1_kernel<<<NIMG, 256>>>(x, c1w, c1b);
    conv2_kernel<<<NIMG, 448, CONV2_SMEM>>>(c2w, c2b);
    fc_kernel<<<64, 256, FC_SMEM>>>(fcw, fcb);
    eq_kernel<<<NIMG, EQ_NT, EQ_SMEM>>>(eqw, eqb);
    final_kernel<<<BB, 64>>>(outw, outb, out);
}

// round 9
// speedup vs baseline: 1.0742x; 1.0742x over previous
#include <cuda_runtime.h>
#include <cuda_bf16.h>
#include <math.h>

#define BB   16
#define KK   32
#define HH   28
#define WW   28
#define HID  64
#define OUT  64
#define NIMG (BB*KK)          // 512

typedef unsigned long long u64;

// ---------------- scratch ----------------
__device__ float g_h1[NIMG * 32 * 14 * 14];
__device__ float g_h2[NIMG * 64 * 7 * 7];
__device__ float g_feat[NIMG * HID];
__device__ float g_part[NIMG * OUT];

// ---------------- packed fp32x2 helpers ----------------
__device__ __forceinline__ u64 pack2(float x, float y) {
    u64 r; asm("mov.b64 %0,{%1,%2};" : "=l"(r) : "f"(x), "f"(y)); return r;
}
__device__ __forceinline__ void unpack2(u64 p, float& x, float& y) {
    asm("mov.b64 {%0,%1},%2;" : "=f"(x), "=f"(y) : "l"(p));
}
__device__ __forceinline__ u64 ffma2(u64 a, u64 b, u64 c) {
    u64 d; asm("fma.rn.f32x2 %0,%1,%2,%3;" : "=l"(d) : "l"(a), "l"(b), "l"(c)); return d;
}
__device__ __forceinline__ u64 fmul2(u64 a, u64 b) {
    u64 d; asm("mul.rn.f32x2 %0,%1,%2;" : "=l"(d) : "l"(a), "l"(b)); return d;
}

// =========================================================================
// Kernel 1: conv1 (1->32, 3x3 SAME) + relu + maxpool2
// =========================================================================
__global__ __launch_bounds__(256) void conv1_kernel(
    const float* __restrict__ x, const float* __restrict__ w,
    const float* __restrict__ bias)
{
    __shared__ float sin1[30 * 30];
    __shared__ float sw1[32 * 9];
    __shared__ float sb1[32];

    const int img = blockIdx.x;
    const int tid = threadIdx.x;

    for (int i = tid; i < 900; i += 256) sin1[i] = 0.f;
    for (int i = tid; i < 288; i += 256) sw1[i] = w[i];
    if (tid < 32) sb1[tid] = bias[tid];
    __syncthreads();
    for (int i = tid; i < 784; i += 256) {
        int y = i / 28, xx = i % 28;
        sin1[(y + 1) * 30 + xx + 1] = x[img * 784 + i];
    }
    __syncthreads();

    for (int item = tid; item < 32 * 196; item += 256) {
        int c = item / 196, p = item % 196;
        int oy = p / 14, ox = p % 14;
        const float* wp = sw1 + c * 9;
        const float bv = sb1[c];
        float m = 0.f;
        #pragma unroll
        for (int py = 0; py < 2; py++) {
            #pragma unroll
            for (int px = 0; px < 2; px++) {
                int r = 2 * oy + py, col = 2 * ox + px;
                float s = bv;
                #pragma unroll
                for (int ky = 0; ky < 3; ky++)
                    #pragma unroll
                    for (int kx = 0; kx < 3; kx++)
                        s += sin1[(r + ky) * 30 + col + kx] * wp[ky * 3 + kx];
                m = fmaxf(m, s);
            }
        }
        g_h1[img * (32 * 196) + item] = m;
    }
}

// =========================================================================
// Kernel 2: conv2 (32->64) + relu + maxpool2. R7 structure (256 thr,
// 2 blocks/SM, warp=pos, lane=ch-pair) + HOISTED packing: patch loaded as
// 8 warp-uniform LDS.64, packed to (v,v) pairs once per ic (not per tap).
// Inner loop: 9 LDS.64 + 36 FFMA2 only.
// =========================================================================
#define CONV2_SMEM ((8192 + 18432 + 64) * 4)
__global__ __launch_bounds__(256, 2) void conv2_kernel(
    const float* __restrict__ w, const float* __restrict__ bias)
{
    extern __shared__ float sm2[];
    float* sin2 = sm2;                 // [ic][16*16], zero-padded border
    float* sw2  = sm2 + 8192;          // [ic*9+r][64ch]
    float* sb2  = sw2 + 18432;

    const int img = blockIdx.x;
    const int tid = threadIdx.x;

    for (int i = tid; i < 8192; i += 256) sin2[i] = 0.f;
    for (int idx = tid; idx < 18432; idx += 256) {
        int f = idx >> 6, c = idx & 63;
        int ic = f / 9, r = f % 9;
        sw2[idx] = w[(c * 32 + ic) * 9 + r];
    }
    if (tid < 64) sb2[tid] = bias[tid];
    __syncthreads();
    for (int i = tid; i < 32 * 196; i += 256) {
        int ic = i / 196, p = i % 196;
        int y = p / 14, xx = p % 14;
        sin2[ic * 256 + (y + 1) * 16 + xx + 1] = g_h1[img * (32 * 196) + i];
    }
    __syncthreads();

    const int wid  = tid >> 5;
    const int lane = tid & 31;
    const int c0   = lane * 2;
    const float b0 = sb2[c0], b1 = sb2[c0 + 1];

    for (int s = 0; s < 7; s++) {
        const int pos = wid + 8 * s;     // warp-uniform
        if (pos >= 49) break;
        const int oy = pos / 7, ox = pos % 7;
        const int iy = 2 * oy, ix = 2 * ox;   // ix even -> float2 aligned

        u64 acc[4];
        #pragma unroll
        for (int p = 0; p < 4; p++) acc[p] = 0ull;

        for (int ic = 0; ic < 32; ic++) {
            const float* ip = sin2 + ic * 256 + iy * 16 + ix;
            u64 pa2[4][4];               // pre-packed (v,v) per ic
            #pragma unroll
            for (int r = 0; r < 4; r++) {
                float2 p0 = *(const float2*)(ip + r * 16);       // broadcast
                float2 p1 = *(const float2*)(ip + r * 16 + 2);   // broadcast
                pa2[r][0] = pack2(p0.x, p0.x);
                pa2[r][1] = pack2(p0.y, p0.y);
                pa2[r][2] = pack2(p1.x, p1.x);
                pa2[r][3] = pack2(p1.y, p1.y);
            }
            const float* wic = sw2 + ic * 576 + c0;
            #pragma unroll
            for (int ky = 0; ky < 3; ky++) {
                #pragma unroll
                for (int kx = 0; kx < 3; kx++) {
                    u64 wv = *(const u64*)(wic + (ky * 3 + kx) * 64);
                    acc[0] = ffma2(pa2[ky][kx],         wv, acc[0]);
                    acc[1] = ffma2(pa2[ky][kx + 1],     wv, acc[1]);
                    acc[2] = ffma2(pa2[ky + 1][kx],     wv, acc[2]);
                    acc[3] = ffma2(pa2[ky + 1][kx + 1], wv, acc[3]);
                }
            }
        }
        float a0[4], a1[4];
        #pragma unroll
        for (int p = 0; p < 4; p++) unpack2(acc[p], a0[p], a1[p]);
        float m0 = fmaxf(fmaxf(a0[0], a0[1]), fmaxf(a0[2], a0[3])) + b0;
        float m1 = fmaxf(fmaxf(a1[0], a1[1]), fmaxf(a1[2], a1[3])) + b1;
        g_h2[img * 3136 + c0 * 49 + pos]       = fmaxf(m0, 0.f);
        g_h2[img * 3136 + (c0 + 1) * 49 + pos] = fmaxf(m1, 0.f);
    }
}

// =========================================================================
// Kernel 3: fc, weight-stationary. 64 blocks x 8 images.
// =========================================================================
#define FC_CHUNK 392
#define FC_WPAD  66
#define FC_SMEM  ((8 * 3136 + FC_CHUNK * FC_WPAD) * 4)
__global__ __launch_bounds__(256) void fc_kernel(
    const float* __restrict__ fcw, const float* __restrict__ fcb)
{
    extern __shared__ float smf[];
    float* sact = smf;                  // [8][3136]
    float* swc  = smf + 8 * 3136;       // [392][66] transposed chunk

    const int tid  = threadIdx.x;
    const int img0 = blockIdx.x * 8;

    for (int idx = tid; idx < 8 * 3136; idx += 256)
        sact[idx] = g_h2[img0 * 3136 + idx];

    const int o2 = (tid & 31) * 2;
    const int q  = tid >> 5;

    u64 acc[8];
    #pragma unroll
    for (int im = 0; im < 8; im++) acc[im] = 0ull;

    for (int ch = 0; ch < 8; ch++) {
        __syncthreads();
        for (int idx = tid; idx < 64 * FC_CHUNK; idx += 256) {
            int o = idx / FC_CHUNK, i = idx % FC_CHUNK;
            swc[i * FC_WPAD + o] = fcw[(size_t)o * 3136 + ch * FC_CHUNK + i];
        }
        __syncthreads();

        const int ibase = q * 49;
        #pragma unroll 7
        for (int t = 0; t < 49; t++) {
            int i = ibase + t;
            u64 wv = *(const u64*)(swc + i * FC_WPAD + o2);
            int gi = ch * FC_CHUNK + i;
            #pragma unroll
            for (int im = 0; im < 8; im++) {
                float a = sact[im * 3136 + gi];
                acc[im] = ffma2(pack2(a, a), wv, acc[im]);
            }
        }
    }
    __syncthreads();

    float* sred = swc;
    #pragma unroll
    for (int im = 0; im < 8; im++) {
        float a0, a1;
        unpack2(acc[im], a0, a1);
        sred[q * 512 + im * 64 + o2]     = a0;
        sred[q * 512 + im * 64 + o2 + 1] = a1;
    }
    __syncthreads();
    for (int idx = tid; idx < 512; idx += 256) {
        int im = idx >> 6, o = idx & 63;
        float s = 0.f;
        #pragma unroll
        for (int qq = 0; qq < 8; qq++) s += sred[qq * 512 + idx];
        g_feat[(img0 + im) * 64 + o] = fmaxf(s + fcb[o], 0.f);
    }
}

// =========================================================================
// Kernel 4: Eq3to3 + relu + mean(ijk). Warp-tile rank-1 outer product +
// duplicated activation store (satdup[d][k]=(v,v)) so the packed aj operand
// comes straight from a broadcast LDS.64 -> no pack MOVs in the d-loop.
// =========================================================================
#define EQ_NT 320
#define EQ_SMEM ((2304 + 4608 + 64 + 3*4352 + 2*2048 + 64 + 640) * 4)
__global__ __launch_bounds__(EQ_NT, 2) void eq_kernel(
    const float* __restrict__ eqw, const float* __restrict__ eqb)
{
    extern __shared__ float sm[];
    float* sat   = sm;             // [d][k] pad 36 : 2304
    float* satd  = sat  + 2304;    // [d][k][2] dup, row stride 72 : 4608
    float* sAb   = satd + 4608;    // 64
    float* sV    = sAb  + 64;      // [d][e] pad 68 : 4352
    float* sCk   = sV   + 4352;
    float* sCj   = sCk  + 4352;
    float* sgk   = sCj  + 4352;    // [k][e] : 2048
    float* sgj   = sgk  + 2048;    // [j][e] : 2048
    float* ssb   = sgj  + 2048;    // 64
    float* sred  = ssb  + 64;      // [10 warps][64]

    const int b   = blockIdx.x >> 5;
    const int ii  = blockIdx.x & 31;
    const int tid = threadIdx.x;

    const float* fb = g_feat + b * KK * HID;
    for (int idx = tid; idx < 2048; idx += EQ_NT) {
        int k = idx >> 6, d = idx & 63;
        float v = fb[idx];
        sat[d * 36 + k] = v;
        *(u64*)(satd + (d * 36 + k) * 2) = pack2(v, v);
    }
    __syncthreads();
    if (tid < 64) {
        const float* row = sat + tid * 36;
        float s = 0.f;
        #pragma unroll
        for (int k = 0; k < 32; k++) s += row[k];
        sAb[tid] = s * (1.0f / 32.0f);
    }
    __syncthreads();

    for (int idx = tid; idx < 4096; idx += EQ_NT) {
        int d = idx >> 6, e = idx & 63;
        const float4* wp = (const float4*)(eqw + (size_t)idx * 8);
        float4 wA = wp[0];   // w0 w1 w2 w3
        float4 wB = wp[1];   // w4 w5 w6 w7
        float ai = sat[d * 36 + ii], ab = sAb[d];
        sV [d * 68 + e] = wA.x * ai + wA.y * ab;
        sCk[d * 68 + e] = ab * (wA.z * ai + wB.x * ab);
        sCj[d * 68 + e] = ab * (wA.w * ai + wB.y * ab);
    }
    if (tid < 64) {
        int e = tid;
        float s = 0.f;
        for (int d = 0; d < 64; d++) {
            float ab = sAb[d];
            float2 w67 = *(const float2*)(eqw + ((size_t)(d * 64 + e)) * 8 + 6);
            s += ab * ab * (w67.x * sat[d * 36 + ii] + w67.y * ab);
        }
        ssb[e] = s + eqb[e];
    }
    __syncthreads();

    for (int idx = tid; idx < 2048; idx += EQ_NT) {
        int k = idx >> 6, e = idx & 63;
        float s1 = 0.f, s2 = 0.f;
        #pragma unroll 8
        for (int d = 0; d < 64; d++) {
            float ak = sat[d * 36 + k];
            s1 += sCk[d * 68 + e] * ak;
            s2 += sCj[d * 68 + e] * ak;
        }
        sgk[k * 64 + e] = s1;
        sgj[k * 64 + e] = s2;
    }
    __syncthreads();

    const int w    = tid >> 5;
    const int lane = tid & 31;

    const u64 JT = 0x3221110000ull;
    const u64 KT = 0x3323213210ull;
    const int jt = (int)((JT >> (4 * w)) & 15);
    const int kt = (int)((KT >> (4 * w)) & 15);
    const int j0 = jt * 8;
    const int k0 = kt * 8;
    const bool diag = (jt == kt);

    float esum0 = 0.f, esum1 = 0.f;

    #pragma unroll
    for (int pass = 0; pass < 2; pass++) {
        const int e = lane + 32 * pass;

        u64 acc[8][4];
        #pragma unroll
        for (int jj = 0; jj < 8; jj++)
            #pragma unroll
            for (int kp = 0; kp < 4; kp++) acc[jj][kp] = 0ull;

        for (int d = 0; d < 64; d++) {
            const float* rd  = sat + d * 36;
            const u64*   rdd = (const u64*)(satd + d * 72);
            float vl = sV[d * 68 + e];               // lane-consecutive
            u64 vlp = pack2(vl, vl);                 // 2 MOVs per d (only)
            u64 ak[4];
            #pragma unroll
            for (int kp = 0; kp < 4; kp++)
                ak[kp] = *(const u64*)(rd + k0 + 2 * kp);          // broadcast

            #pragma unroll
            for (int jj = 0; jj < 8; jj++) {
                u64 ajp = rdd[j0 + jj];              // (aj,aj) broadcast LDS.64
                u64 tp = fmul2(ajp, vlp);
                acc[jj][0] = ffma2(tp, ak[0], acc[jj][0]);
                acc[jj][1] = ffma2(tp, ak[1], acc[jj][1]);
                acc[jj][2] = ffma2(tp, ak[2], acc[jj][2]);
                acc[jj][3] = ffma2(tp, ak[3], acc[jj][3]);
            }
        }

        const float sbv = ssb[e];
        float es = 0.f;
        #pragma unroll
        for (int jj = 0; jj < 8; jj++) {
            const int j = j0 + jj;
            const float gjj = sgj[j * 64 + e];
            const float gkj = sgk[j * 64 + e];
            #pragma unroll
            for (int kp = 0; kp < 4; kp++) {
                float a0, a1;
                unpack2(acc[jj][kp], a0, a1);
                const int ka = k0 + 2 * kp;
                const int kb = ka + 1;
                float gkka = sgk[ka * 64 + e], gjka = sgj[ka * 64 + e];
                float gkkb = sgk[kb * 64 + e], gjkb = sgj[kb * 64 + e];
                float p0 = a0 + gjj + gkka + sbv;
                float q0 = a0 + gjka + gkj + sbv;
                float p1 = a1 + gjj + gkkb + sbv;
                float q1 = a1 + gjkb + gkj + sbv;
                if (!diag || ka >= j) es += fmaxf(p0, 0.f);
                if (!diag || ka >  j) es += fmaxf(q0, 0.f);
                if (!diag || kb >= j) es += fmaxf(p1, 0.f);
                if (!diag || kb >  j) es += fmaxf(q1, 0.f);
            }
        }
        if (pass == 0) esum0 = es; else esum1 = es;
    }

    sred[w * 64 + lane]      = esum0;
    sred[w * 64 + lane + 32] = esum1;
    __syncthreads();
    if (tid < 64) {
        float s = 0.f;
        #pragma unroll
        for (int g = 0; g < 10; g++) s += sred[g * 64 + tid];
        g_part[blockIdx.x * 64 + tid] = s;
    }
}

// =========================================================================
// Kernel 5: final
// =========================================================================
__global__ __launch_bounds__(64) void final_kernel(
    const float* __restrict__ outw, const float* __restrict__ outb,
    float* __restrict__ out)
{
    __shared__ float red[64];
    const int b = blockIdx.x, e = threadIdx.x;
    float s = 0.f;
    #pragma unroll
    for (int i = 0; i < 32; i++) s += g_part[(b * 32 + i) * 64 + e];
    float x8 = s * (1.0f / 32768.0f);
    red[e] = fmaxf(x8, 0.f) * outw[e];
    __syncthreads();
    #pragma unroll
    for (int off = 32; off; off >>= 1) {
        if (e < off) red[e] += red[e + off];
        __syncthreads();
    }
    if (e == 0) out[b] = red[0] + outb[0];
}

// =========================================================================
extern "C" void kernel_launch(void* const* d_in, const int* in_sizes, int n_in,
                              void* d_out, int out_size)
{
    const float* x    = (const float*)d_in[0];
    const float* c1w  = (const float*)d_in[1];
    const float* c1b  = (const float*)d_in[2];
    const float* c2w  = (const float*)d_in[3];
    const float* c2b  = (const float*)d_in[4];
    const float* fcw  = (const float*)d_in[5];
    const float* fcb  = (const float*)d_in[6];
    const float* eqw  = (const float*)d_in[7];
    const float* eqb  = (const float*)d_in[8];
    const float* outw = (const float*)d_in[9];
    const float* outb = (const float*)d_in[10];
    float* out = (float*)d_out;

    cudaFuncSetAttribute(conv2_kernel, cudaFuncAttributeMaxDynamicSharedMemorySize, CONV2_SMEM);
    cudaFuncSetAttribute(fc_kernel,    cudaFuncAttributeMaxDynamicSharedMemorySize, FC_SMEM);
    cudaFuncSetAttribute(eq_kernel,    cudaFuncAttributeMaxDynamicSharedMemorySize, EQ_SMEM);

    conv1_kernel<<<NIMG, 256>>>(x, c1w, c1b);
    conv2_kernel<<<NIMG, 256, CONV2_SMEM>>>(c2w, c2b);
    fc_kernel<<<64, 256, FC_SMEM>>>(fcw, fcb);
    eq_kernel<<<NIMG, EQ_NT, EQ_SMEM>>>(eqw, eqb);
    final_kernel<<<BB, 64>>>(outw, outb, out);
}